// round 9
// baseline (speedup 1.0000x reference)
#include <cuda_runtime.h>
#include <cuda_bf16.h>
#include <cstdint>
#include <cfloat>

// Problem constants
#define BB 8192
#define CC 64
#define KK 256
#define DD 64
#define N1 (BB*CC)            // 524288
#define NCENT (CC*KK*DD)      // 1048576
#define TTILES 4
#define NGX 16                // BB / (128*TTILES)
#define NGX2 (NGX*2)          // stats partials per channel (16 gx x 2 halves)

// -------- static device scratch (no allocations allowed) --------
__device__ __align__(16) __nv_bfloat16 g_cb0[NCENT];   // h split, [c][k][d]
__device__ __align__(16) __nv_bfloat16 g_cb1[NCENT];   // m split
__device__ __align__(16) __nv_bfloat16 g_cb2[NCENT];   // l split
__device__ float  g_cv[2*N1];      // per-half candidate value, [half][c][b]
__device__ int    g_ci[2*N1];      // per-half candidate k (global index)
__device__ float2 g_part[CC*NGX2];
__device__ float  g_mean[CC];
__device__ float  g_invstd[CC];

// ---------------- smem layout (dynamic) ----------------
// Per block (K-half): B 3 splits x 16KB + A (single buf) 3 splits x 16KB
#define SM_B      0u        // 3 x 16384  (128 k-rows x 128B, swizzled)
#define SM_A      49152u    // 3 x 16384  (128 b-rows x 128B, swizzled)
#define A_SPLIT   16384u
#define SM_CAND   98304u    // 128 rows x 2 warpN x float2 = 2048
#define SM_RED    100352u   // 8 x float2
#define SM_TOTAL  100416u   // ~98KB -> 2 blocks/SM

#define SWZ(o) ((uint32_t)(o) ^ ((((uint32_t)(o))>>3)&0x70u))

// ---------------- PTX helpers (portable sm_80+ only) ----------------
static __device__ __forceinline__ uint32_t smem_u32(const void* p){
    uint32_t a;
    asm("{ .reg .u64 t; cvta.to.shared.u64 t, %1; cvt.u32.u64 %0, t; }"
        : "=r"(a) : "l"(p));
    return a;
}
static __device__ __forceinline__ void ldsm4(uint32_t* r, uint32_t addr){
    asm volatile("ldmatrix.sync.aligned.m8n8.x4.shared.b16 {%0,%1,%2,%3}, [%4];"
        : "=r"(r[0]), "=r"(r[1]), "=r"(r[2]), "=r"(r[3]) : "r"(addr));
}
static __device__ __forceinline__ void mma16816(float* c, const uint32_t* a,
                                                uint32_t b0, uint32_t b1){
    asm volatile(
        "mma.sync.aligned.m16n8k16.row.col.f32.bf16.bf16.f32 "
        "{%0,%1,%2,%3}, {%4,%5,%6,%7}, {%8,%9}, {%0,%1,%2,%3};"
        : "+f"(c[0]), "+f"(c[1]), "+f"(c[2]), "+f"(c[3])
        : "r"(a[0]), "r"(a[1]), "r"(a[2]), "r"(a[3]), "r"(b0), "r"(b1));
}

// ---------------- conversion helpers ----------------
static __device__ __forceinline__ void split3(float x, __nv_bfloat16& h,
                                              __nv_bfloat16& m, __nv_bfloat16& l){
    h = __float2bfloat16_rn(x);
    float r1 = x - __bfloat162float(h);
    m = __float2bfloat16_rn(r1);
    float r2 = r1 - __bfloat162float(m);
    l = __float2bfloat16_rn(r2);
}
static __device__ __forceinline__ uint32_t pk(__nv_bfloat16 a, __nv_bfloat16 b){
    __nv_bfloat162 t = __halves2bfloat162(a, b);
    return *reinterpret_cast<uint32_t*>(&t);
}

// load one 128x64 fp32 A tile into registers (32 floats / thread)
static __device__ __forceinline__ void loadX(float4* xr, const float* __restrict__ x,
                                             int gx, int c, int t, int tid){
    const int b0 = (gx*TTILES + t)*128;
    const int q8 = tid & 7;
    #pragma unroll
    for (int i = 0; i < 4; ++i){
        int row = i*32 + (tid >> 3);
        const float4* xp = (const float4*)x + ((size_t)(b0+row)*CC + c)*(DD/4) + q8*2;
        xr[2*i]   = xp[0];
        xr[2*i+1] = xp[1];
    }
}
// convert registers -> 3 bf16 splits in smem (single A buffer)
static __device__ __forceinline__ void storeSplits(char* sm, const float4* xr, int tid){
    const int q8 = tid & 7;
    #pragma unroll
    for (int i = 0; i < 4; ++i){
        int row = i*32 + (tid >> 3);
        float f[8] = {xr[2*i].x, xr[2*i].y, xr[2*i].z, xr[2*i].w,
                      xr[2*i+1].x, xr[2*i+1].y, xr[2*i+1].z, xr[2*i+1].w};
        uint32_t H[4], M[4], L[4];
        #pragma unroll
        for (int pi = 0; pi < 4; ++pi){
            __nv_bfloat16 h0,m0,l0,h1,m1,l1;
            split3(f[2*pi],   h0, m0, l0);
            split3(f[2*pi+1], h1, m1, l1);
            H[pi] = pk(h0,h1); M[pi] = pk(m0,m1); L[pi] = pk(l0,l1);
        }
        uint32_t so = SWZ(row*128 + q8*16);
        *(uint4*)(sm + SM_A + so)             = make_uint4(H[0],H[1],H[2],H[3]);
        *(uint4*)(sm + SM_A + A_SPLIT + so)   = make_uint4(M[0],M[1],M[2],M[3]);
        *(uint4*)(sm + SM_A + 2*A_SPLIT + so) = make_uint4(L[0],L[1],L[2],L[3]);
    }
}

// ---------------------------------------------------------------------------
// Main kernel: grid (NGX, CC, 2) — z = K-half. 256 threads, warps 4(m) x 2(n),
// warp n-tile 32 wide, K-half of 128 processed as two 64-wide nh passes.
// 6-pass bf16 split GEMM on mma.sync; 2 blocks/SM (98KB smem, <=128 regs).
//   sb=2 (l): {h*l}   sb=1 (m): {m*m, h*m}   sb=0 (h): {l*h, m*h, h*h}
// ---------------------------------------------------------------------------
__global__ __launch_bounds__(256, 2)
void mma_kernel(const float* __restrict__ x, const float* __restrict__ gamma){
    extern __shared__ __align__(16) char sm[];
    const uint32_t smb = smem_u32(sm);
    const int tid = threadIdx.x, lane = tid & 31, wid = tid >> 5;
    const int warpM = wid >> 1, warpN = wid & 1, q = lane >> 2;
    const int gx = blockIdx.x, c = blockIdx.y, half = blockIdx.z;

    // ---- load this K-half's 3 B splits into swizzled smem (48KB) ----
    {
        const uint4* cb0 = (const uint4*)g_cb0;
        const uint4* cb1 = (const uint4*)g_cb1;
        const uint4* cb2 = (const uint4*)g_cb2;
        #pragma unroll
        for (int i = 0; i < 12; ++i){
            int flat = i*256 + tid;          // 0..3071
            int s    = flat >> 10;
            int g    = flat & 1023;
            int row  = g >> 3, q8 = g & 7;
            const uint4* src = (s==0) ? cb0 : (s==1) ? cb1 : cb2;
            uint4 v = src[((size_t)c*KK + half*128 + row)*8 + q8];
            *(uint4*)(sm + SM_B + (uint32_t)s*16384u + SWZ(row*128 + q8*16)) = v;
        }
    }

    const float gmm = gamma[c];
    const bool wantMin = (gmm < 0.f);
    float sum = 0.f, sum2 = 0.f;

    // per-lane ldmatrix address components
    const uint32_t aRow  = (uint32_t)(warpM*32 + (lane & 15));
    const uint32_t aCol  = (uint32_t)((lane >> 4) << 4);       // 0 or 16 bytes
    const uint32_t bRowL = (uint32_t)(((lane >> 4) << 3) + (lane & 7));
    const uint32_t bCol  = (uint32_t)((lane & 8) << 1);        // 0 or 16 bytes

    // 6-pass tables grouped by B split (low-magnitude first within each group)
    const int SBt[3] = {2, 1, 0};
    const int SAt[3][3] = {{0,-1,-1},{1,0,-1},{2,1,0}};

    float2* cand = (float2*)(sm + SM_CAND);

    float4 xr[8];
    loadX(xr, x, gx, c, 0, tid);

    #pragma unroll 1
    for (int t = 0; t < TTILES; ++t){
        storeSplits(sm, xr, tid);
        __syncthreads();                 // A(t) ready (also: cand(t-1) consumed)

        float rE[4]; int rI[4];
        #pragma unroll
        for (int s4 = 0; s4 < 4; ++s4){
            rE[s4] = wantMin ? FLT_MAX : -FLT_MAX; rI[s4] = 0;
        }

        #pragma unroll
        for (int nh = 0; nh < 2; ++nh){
            float acc[2][4][4];
            #pragma unroll
            for (int mi = 0; mi < 2; ++mi)
                #pragma unroll
                for (int nj = 0; nj < 4; ++nj)
                    #pragma unroll
                    for (int e = 0; e < 4; ++e) acc[mi][nj][e] = 0.f;

            #pragma unroll
            for (int ks = 0; ks < 4; ++ks){
                uint32_t aF[3][2][4];
                #pragma unroll
                for (int s = 0; s < 3; ++s)
                    #pragma unroll
                    for (int mi = 0; mi < 2; ++mi)
                        ldsm4(aF[s][mi], smb + SM_A + (uint32_t)s*16384u +
                              SWZ(aRow*128u + (uint32_t)mi*2048u +
                                  (uint32_t)ks*32u + aCol));
                #pragma unroll
                for (int g3 = 0; g3 < 3; ++g3){
                    const int sb = SBt[g3];
                    uint32_t bF[2][4];
                    #pragma unroll
                    for (int njp = 0; njp < 2; ++njp)
                        ldsm4(bF[njp], smb + SM_B + (uint32_t)sb*16384u +
                              SWZ((uint32_t)(nh*64 + warpN*32 + njp*16 + bRowL)*128u +
                                  (uint32_t)ks*32u + bCol));
                    #pragma unroll
                    for (int pi = 0; pi < 3; ++pi){
                        const int sa = SAt[g3][pi];
                        if (sa < 0) continue;
                        #pragma unroll
                        for (int mi = 0; mi < 2; ++mi)
                            #pragma unroll
                            for (int njp = 0; njp < 2; ++njp){
                                mma16816(acc[mi][2*njp],   aF[sa][mi], bF[njp][0], bF[njp][1]);
                                mma16816(acc[mi][2*njp+1], aF[sa][mi], bF[njp][2], bF[njp][3]);
                            }
                    }
                }
            }

            // ---- epilogue scan (local k within this K-half) ----
            const int kbase = nh*64 + warpN*32 + 2*(lane & 3);
            if (!wantMin){
                #pragma unroll
                for (int mi = 0; mi < 2; ++mi)
                    #pragma unroll
                    for (int nj = 0; nj < 4; ++nj){
                        const int k0 = kbase + nj*8;
                        float v0 = acc[mi][nj][0], v1 = acc[mi][nj][1];
                        float v2 = acc[mi][nj][2], v3 = acc[mi][nj][3];
                        sum += v0 + v1 + v2 + v3;
                        sum2 = fmaf(v0, v0, sum2); sum2 = fmaf(v1, v1, sum2);
                        sum2 = fmaf(v2, v2, sum2); sum2 = fmaf(v3, v3, sum2);
                        const int s0 = mi*2, s1 = mi*2 + 1;
                        if (v0 > rE[s0]){ rE[s0] = v0; rI[s0] = k0;   }
                        if (v1 > rE[s0]){ rE[s0] = v1; rI[s0] = k0+1; }
                        if (v2 > rE[s1]){ rE[s1] = v2; rI[s1] = k0;   }
                        if (v3 > rE[s1]){ rE[s1] = v3; rI[s1] = k0+1; }
                    }
            } else {
                #pragma unroll
                for (int mi = 0; mi < 2; ++mi)
                    #pragma unroll
                    for (int nj = 0; nj < 4; ++nj){
                        const int k0 = kbase + nj*8;
                        float v0 = acc[mi][nj][0], v1 = acc[mi][nj][1];
                        float v2 = acc[mi][nj][2], v3 = acc[mi][nj][3];
                        sum += v0 + v1 + v2 + v3;
                        sum2 = fmaf(v0, v0, sum2); sum2 = fmaf(v1, v1, sum2);
                        sum2 = fmaf(v2, v2, sum2); sum2 = fmaf(v3, v3, sum2);
                        const int s0 = mi*2, s1 = mi*2 + 1;
                        if (v0 < rE[s0]){ rE[s0] = v0; rI[s0] = k0;   }
                        if (v1 < rE[s0]){ rE[s0] = v1; rI[s0] = k0+1; }
                        if (v2 < rE[s1]){ rE[s1] = v2; rI[s1] = k0;   }
                        if (v3 < rE[s1]){ rE[s1] = v3; rI[s1] = k0+1; }
                    }
            }
        }

        // prefetch next x tile (placed here: xr dead during MMA loop above)
        if (t+1 < TTILES) loadX(xr, x, gx, c, t+1, tid);

        // ---- cross-lane (quad) reduce, write candidates ----
        #pragma unroll
        for (int s4 = 0; s4 < 4; ++s4){
            float ev = rE[s4]; int ei = rI[s4];
            #pragma unroll
            for (int off = 1; off <= 2; off <<= 1){
                float ov = __shfl_xor_sync(0xffffffffu, ev, off);
                int   oi = __shfl_xor_sync(0xffffffffu, ei, off);
                bool take = wantMin ? (ov < ev || (ov == ev && oi < ei))
                                    : (ov > ev || (ov == ev && oi < ei));
                if (take){ ev = ov; ei = oi; }
            }
            if ((lane & 3) == 0){
                int row = warpM*32 + (s4 >> 1)*16 + (s4 & 1)*8 + q;
                cand[row*2 + warpN] = make_float2(ev, __int_as_float(ei));
            }
        }
        __syncthreads();   // cand(t) ready; all warps done reading A(t)

        // ---- merge across the two n-warps, write per-half candidates ----
        if (tid < 128){
            float2 c0 = cand[tid*2 + 0], c1 = cand[tid*2 + 1];
            float ev = c0.x; int ei = __float_as_int(c0.y);
            int   oi = __float_as_int(c1.y);
            bool take = wantMin ? (c1.x < ev || (c1.x == ev && oi < ei))
                                : (c1.x > ev || (c1.x == ev && oi < ei));
            if (take){ ev = c1.x; ei = oi; }
            const int b = (gx*TTILES + t)*128 + tid;
            size_t o = (size_t)half*N1 + (size_t)c*BB + b;
            g_cv[o] = ev;
            g_ci[o] = half*128 + ei;    // global k index
        }
    }

    // ---- per-block stats partial (deterministic) ----
    #pragma unroll
    for (int off = 16; off; off >>= 1){
        sum  += __shfl_xor_sync(0xffffffffu, sum,  off);
        sum2 += __shfl_xor_sync(0xffffffffu, sum2, off);
    }
    float2* red = (float2*)(sm + SM_RED);
    if (lane == 0) red[wid] = make_float2(sum, sum2);
    __syncthreads();
    if (tid == 0){
        float s = 0.f, s2 = 0.f;
        #pragma unroll
        for (int w = 0; w < 8; ++w){ s += red[w].x; s2 += red[w].y; }
        g_part[c*NGX2 + gx*2 + half] = make_float2(s, s2);
    }
}

// ---------------------------------------------------------------------------
// Prep: centroid bf16 3-way splits + centroids passthrough to out
// ---------------------------------------------------------------------------
__global__ void prep_kernel(const float4* __restrict__ cent,
                            float4* __restrict__ outc){
    int i = blockIdx.x*256 + threadIdx.x;    // < NCENT/4
    float4 v = cent[i];
    outc[i] = v;
    float f[4] = {v.x, v.y, v.z, v.w};
    __nv_bfloat16 h[4], m[4], l[4];
    #pragma unroll
    for (int p = 0; p < 4; ++p) split3(f[p], h[p], m[p], l[p]);
    ((uint2*)g_cb0)[i] = make_uint2(pk(h[0],h[1]), pk(h[2],h[3]));
    ((uint2*)g_cb1)[i] = make_uint2(pk(m[0],m[1]), pk(m[2],m[3]));
    ((uint2*)g_cb2)[i] = make_uint2(pk(l[0],l[1]), pk(l[2],l[3]));
}

// ---------------------------------------------------------------------------
// Stats reduce: 32 partials per channel -> mean, invstd
// ---------------------------------------------------------------------------
__global__ void pass2_kernel(){
    int c = threadIdx.x;
    if (c < CC){
        double s = 0.0, s2 = 0.0;
        for (int i = 0; i < NGX2; ++i){
            float2 p = g_part[c*NGX2 + i];
            s += (double)p.x; s2 += (double)p.y;
        }
        const double cnt = (double)BB*(double)KK;
        double mean = s / cnt;
        double var  = s2 / cnt - mean*mean;
        g_mean[c]   = (float)mean;
        g_invstd[c] = rsqrtf((float)var + 1e-5f);
    }
}

// ---------------------------------------------------------------------------
// Finalize: merge K-halves, normalize, transpose [c][b] -> [b][c], write out
// ---------------------------------------------------------------------------
__global__ __launch_bounds__(256)
void pass3_kernel(const float* __restrict__ gamma, const float* __restrict__ beta,
                  float* __restrict__ out){
    __shared__ float tc[16][65];
    __shared__ float tv[16][65];
    const int tid = threadIdx.x;
    const int b0  = blockIdx.x*16;
    #pragma unroll
    for (int i = 0; i < 4; ++i){
        int flat = i*256 + tid;           // 0..1023
        int cc = flat >> 4, bq = flat & 15;
        int b  = b0 + bq;
        float g = gamma[cc];
        size_t o0 = (size_t)cc*BB + b;
        float v0 = g_cv[o0],      v1 = g_cv[N1 + o0];
        int   i0 = g_ci[o0],      i1 = g_ci[N1 + o0];
        // half-1 indices are always larger: strict compare keeps first-occurrence
        bool take = (g < 0.f) ? (v1 < v0) : (v1 > v0);
        float ev = take ? v1 : v0;
        int   ei = take ? i1 : i0;
        float code, val;
        if (g != 0.f){
            code = (float)ei;
            val  = (ev - g_mean[cc])*g_invstd[cc]*g + beta[cc];
        } else {
            code = 0.f;
            val  = beta[cc];
        }
        tc[bq][cc] = code;
        tv[bq][cc] = val;
    }
    __syncthreads();
    #pragma unroll
    for (int i = 0; i < 4; ++i){
        int flat = i*256 + tid;
        int row = flat >> 6, cc = flat & 63;
        size_t o = (size_t)(b0 + row)*CC + cc;
        out[o]      = tc[row][cc];
        out[N1 + o] = tv[row][cc];
    }
}

// ---------------------------------------------------------------------------
extern "C" void kernel_launch(void* const* d_in, const int* in_sizes, int n_in,
                              void* d_out, int out_size){
    (void)in_sizes; (void)n_in; (void)out_size;
    const float* x     = (const float*)d_in[0];
    const float* cent  = (const float*)d_in[1];
    const float* gamma = (const float*)d_in[2];
    const float* beta  = (const float*)d_in[3];
    float* out = (float*)d_out;

    cudaFuncSetAttribute(mma_kernel,
                         cudaFuncAttributeMaxDynamicSharedMemorySize, SM_TOTAL);

    prep_kernel<<<NCENT/4/256, 256>>>((const float4*)cent,
                                      (float4*)(out + 2*(size_t)N1));
    mma_kernel<<<dim3(NGX, CC, 2), 256, SM_TOTAL>>>(x, gamma);
    pass2_kernel<<<1, 64>>>();
    pass3_kernel<<<BB/16, 256>>>(gamma, beta, out);
}

// round 10
// speedup vs baseline: 1.0735x; 1.0735x over previous
#include <cuda_runtime.h>
#include <cuda_bf16.h>
#include <cstdint>
#include <cfloat>

// Problem constants
#define BB 8192
#define CC 64
#define KK 256
#define DD 64
#define N1 (BB*CC)            // 524288
#define NCENT (CC*KK*DD)      // 1048576
#define TTILES 4
#define NGX 16                // BB / (128*TTILES)

// -------- static device scratch (no allocations allowed) --------
__device__ __align__(16) __nv_bfloat16 g_cb0[NCENT];   // h split, [c][k][d]
__device__ __align__(16) __nv_bfloat16 g_cb1[NCENT];   // m split
__device__ __align__(16) __nv_bfloat16 g_cb2[NCENT];   // l split
__device__ int    g_codei[N1];     // [c][b]
__device__ float  g_selv[N1];      // [c][b]
__device__ float2 g_part[CC*NGX];
__device__ float  g_mean[CC];
__device__ float  g_invstd[CC];

// ---------------- smem layout (dynamic) ----------------
#define SM_B      0u        // 3 splits x 32768  (256 rows x 128B, swizzled)
#define SM_A      98304u    // 2 bufs x 3 splits x 16384
#define A_BUF     49152u
#define A_SPLIT   16384u
#define SM_CAND   196608u   // 2 bufs x (128 rows x 2 warpN x float2)
#define CAND_BUF  2048u
#define SM_RED    200704u   // 8 x float2
#define SM_TOTAL  200768u

#define SWZ(o) ((uint32_t)(o) ^ ((((uint32_t)(o))>>3)&0x70u))

// per-warp-pair named barrier (64 threads; ids 1..4)
#define PBAR(p) asm volatile("bar.sync %0, 64;" :: "r"((p)+1) : "memory")

// ---------------- PTX helpers (portable sm_80+ only) ----------------
static __device__ __forceinline__ uint32_t smem_u32(const void* p){
    uint32_t a;
    asm("{ .reg .u64 t; cvta.to.shared.u64 t, %1; cvt.u32.u64 %0, t; }"
        : "=r"(a) : "l"(p));
    return a;
}
static __device__ __forceinline__ void ldsm4(uint32_t* r, uint32_t addr){
    asm volatile("ldmatrix.sync.aligned.m8n8.x4.shared.b16 {%0,%1,%2,%3}, [%4];"
        : "=r"(r[0]), "=r"(r[1]), "=r"(r[2]), "=r"(r[3]) : "r"(addr));
}
static __device__ __forceinline__ void mma16816(float* c, const uint32_t* a,
                                                uint32_t b0, uint32_t b1){
    asm volatile(
        "mma.sync.aligned.m16n8k16.row.col.f32.bf16.bf16.f32 "
        "{%0,%1,%2,%3}, {%4,%5,%6,%7}, {%8,%9}, {%0,%1,%2,%3};"
        : "+f"(c[0]), "+f"(c[1]), "+f"(c[2]), "+f"(c[3])
        : "r"(a[0]), "r"(a[1]), "r"(a[2]), "r"(a[3]), "r"(b0), "r"(b1));
}

// ---------------- conversion helpers ----------------
static __device__ __forceinline__ void split3(float x, __nv_bfloat16& h,
                                              __nv_bfloat16& m, __nv_bfloat16& l){
    h = __float2bfloat16_rn(x);
    float r1 = x - __bfloat162float(h);
    m = __float2bfloat16_rn(r1);
    float r2 = r1 - __bfloat162float(m);
    l = __float2bfloat16_rn(r2);
}
static __device__ __forceinline__ uint32_t pk(__nv_bfloat16 a, __nv_bfloat16 b){
    __nv_bfloat162 t = __halves2bfloat162(a, b);
    return *reinterpret_cast<uint32_t*>(&t);
}

// ---- pair-local x load: each 64-thread pair loads its own 32 A-rows ----
// 16 lanes per row (one float4 each) -> fully coalesced 256B per row.
static __device__ __forceinline__ void loadX(float4* xr, const float* __restrict__ x,
                                             int gx, int c, int t,
                                             int pair, int pairTid){
    const int b0 = (gx*TTILES + t)*128;
    const int f4 = pairTid & 15;
    #pragma unroll
    for (int i = 0; i < 8; ++i){
        int row = pair*32 + i*4 + (pairTid >> 4);
        xr[i] = ((const float4*)x)[((size_t)(b0+row)*CC + c)*(DD/4) + f4];
    }
}
// ---- pair-local convert: registers -> 3 bf16 splits in smem buffer ----
static __device__ __forceinline__ void storeSplits(char* sm, uint32_t abase,
                                                   const float4* xr,
                                                   int pair, int pairTid){
    const int f4 = pairTid & 15;
    #pragma unroll
    for (int i = 0; i < 8; ++i){
        int row = pair*32 + i*4 + (pairTid >> 4);
        float f[4] = {xr[i].x, xr[i].y, xr[i].z, xr[i].w};
        __nv_bfloat16 h[4], m[4], l[4];
        #pragma unroll
        for (int p = 0; p < 4; ++p) split3(f[p], h[p], m[p], l[p]);
        uint32_t so = SWZ(row*128 + f4*8);
        *(uint2*)(sm + abase + so)             = make_uint2(pk(h[0],h[1]), pk(h[2],h[3]));
        *(uint2*)(sm + abase + A_SPLIT + so)   = make_uint2(pk(m[0],m[1]), pk(m[2],m[3]));
        *(uint2*)(sm + abase + 2*A_SPLIT + so) = make_uint2(pk(l[0],l[1]), pk(l[2],l[3]));
    }
}

// ---------------------------------------------------------------------------
// Main kernel: grid (NGX, CC), 256 threads, warp grid 4(m) x 2(n),
// warp tile 32x64, N in two 128-halves. 6-pass bf16 split GEMM on mma.sync.
//   sb=2 (l): {h*l}   sb=1 (m): {m*m, h*m}   sb=0 (h): {l*h, m*h, h*h}
// Each 64-thread warp-pair (one warpM) owns its 32 A rows end-to-end:
// load, convert, MMA, scan, merge — synced by a pair-local named barrier,
// so the four pairs stagger and cover each other's non-MMA phases.
// ---------------------------------------------------------------------------
__global__ __launch_bounds__(256, 1)
void mma_kernel(const float* __restrict__ x, const float* __restrict__ gamma){
    extern __shared__ __align__(16) char sm[];
    const uint32_t smb = smem_u32(sm);
    const int tid = threadIdx.x, lane = tid & 31, wid = tid >> 5;
    const int warpM = wid >> 1, warpN = wid & 1, q = lane >> 2;
    const int pair = warpM, pairTid = tid & 63;
    const int gx = blockIdx.x, c = blockIdx.y;

    // ---- load 3 B splits into swizzled smem (96KB, whole block) ----
    {
        const uint4* cb0 = (const uint4*)g_cb0;
        const uint4* cb1 = (const uint4*)g_cb1;
        const uint4* cb2 = (const uint4*)g_cb2;
        #pragma unroll
        for (int i = 0; i < 24; ++i){
            int flat = i*256 + tid;          // 0..6143
            int s    = flat >> 11;
            int g    = flat & 2047;
            int row  = g >> 3, q8 = g & 7;
            const uint4* src = (s==0) ? cb0 : (s==1) ? cb1 : cb2;
            uint4 v = src[((size_t)c*KK + row)*8 + q8];
            *(uint4*)(sm + SM_B + (uint32_t)s*32768u + SWZ(row*128 + q8*16)) = v;
        }
    }

    const float gmm = gamma[c];
    const bool wantMin = (gmm < 0.f);
    float sum = 0.f, sum2 = 0.f;

    // per-lane ldmatrix address components
    const uint32_t aRow  = (uint32_t)(warpM*32 + (lane & 15));
    const uint32_t aCol  = (uint32_t)((lane >> 4) << 4);       // 0 or 16 bytes
    const uint32_t bRowL = (uint32_t)(((lane >> 4) << 3) + (lane & 7));
    const uint32_t bCol  = (uint32_t)((lane & 8) << 1);        // 0 or 16 bytes

    // 6-pass tables grouped by B split (low-magnitude first within each group)
    const int SBt[3] = {2, 1, 0};
    const int SAt[3][3] = {{0,-1,-1},{1,0,-1},{2,1,0}};

    // prologue: load + convert tile 0 (pair-local rows); full sync covers B too
    float4 xr[8];
    loadX(xr, x, gx, c, 0, pair, pairTid);
    storeSplits(sm, SM_A, xr, pair, pairTid);
    __syncthreads();

    #pragma unroll 1
    for (int t = 0; t < TTILES; ++t){
        // prefetch next x tile into registers (hidden under compute)
        if (t+1 < TTILES) loadX(xr, x, gx, c, t+1, pair, pairTid);

        const uint32_t abase = SM_A + (uint32_t)(t&1)*A_BUF;
        float2* cand = (float2*)(sm + SM_CAND + (uint32_t)(t&1)*CAND_BUF);

        // single-extremum running candidates per owned row-slot
        float rE[4]; int rI[4];
        #pragma unroll
        for (int s4 = 0; s4 < 4; ++s4){
            rE[s4] = wantMin ? FLT_MAX : -FLT_MAX; rI[s4] = 0;
        }

        #pragma unroll
        for (int nh = 0; nh < 2; ++nh){
            float acc[2][8][4];
            #pragma unroll
            for (int mi = 0; mi < 2; ++mi)
                #pragma unroll
                for (int nj = 0; nj < 8; ++nj)
                    #pragma unroll
                    for (int e = 0; e < 4; ++e) acc[mi][nj][e] = 0.f;

            #pragma unroll
            for (int ks = 0; ks < 4; ++ks){
                uint32_t aF[3][2][4];
                #pragma unroll
                for (int s = 0; s < 3; ++s)
                    #pragma unroll
                    for (int mi = 0; mi < 2; ++mi)
                        ldsm4(aF[s][mi], smb + abase + (uint32_t)s*16384u +
                              SWZ(aRow*128u + (uint32_t)mi*2048u +
                                  (uint32_t)ks*32u + aCol));
                #pragma unroll
                for (int g3 = 0; g3 < 3; ++g3){
                    const int sb = SBt[g3];
                    uint32_t bF[4][4];
                    #pragma unroll
                    for (int njp = 0; njp < 4; ++njp)
                        ldsm4(bF[njp], smb + SM_B + (uint32_t)sb*32768u +
                              SWZ((uint32_t)(nh*128 + warpN*64 + njp*16 + bRowL)*128u +
                                  (uint32_t)ks*32u + bCol));
                    #pragma unroll
                    for (int pi = 0; pi < 3; ++pi){
                        const int sa = SAt[g3][pi];
                        if (sa < 0) continue;
                        #pragma unroll
                        for (int mi = 0; mi < 2; ++mi)
                            #pragma unroll
                            for (int njp = 0; njp < 4; ++njp){
                                mma16816(acc[mi][2*njp],   aF[sa][mi], bF[njp][0], bF[njp][1]);
                                mma16816(acc[mi][2*njp+1], aF[sa][mi], bF[njp][2], bF[njp][3]);
                            }
                    }
                }
            }

            // ---- epilogue scan (uniform branch: track only needed extremum) ----
            const int kbase = nh*128 + warpN*64 + 2*(lane & 3);
            if (!wantMin){
                #pragma unroll
                for (int mi = 0; mi < 2; ++mi)
                    #pragma unroll
                    for (int nj = 0; nj < 8; ++nj){
                        const int k0 = kbase + nj*8;
                        float v0 = acc[mi][nj][0], v1 = acc[mi][nj][1];
                        float v2 = acc[mi][nj][2], v3 = acc[mi][nj][3];
                        sum += v0 + v1 + v2 + v3;
                        sum2 = fmaf(v0, v0, sum2); sum2 = fmaf(v1, v1, sum2);
                        sum2 = fmaf(v2, v2, sum2); sum2 = fmaf(v3, v3, sum2);
                        const int s0 = mi*2, s1 = mi*2 + 1;
                        if (v0 > rE[s0]){ rE[s0] = v0; rI[s0] = k0;   }
                        if (v1 > rE[s0]){ rE[s0] = v1; rI[s0] = k0+1; }
                        if (v2 > rE[s1]){ rE[s1] = v2; rI[s1] = k0;   }
                        if (v3 > rE[s1]){ rE[s1] = v3; rI[s1] = k0+1; }
                    }
            } else {
                #pragma unroll
                for (int mi = 0; mi < 2; ++mi)
                    #pragma unroll
                    for (int nj = 0; nj < 8; ++nj){
                        const int k0 = kbase + nj*8;
                        float v0 = acc[mi][nj][0], v1 = acc[mi][nj][1];
                        float v2 = acc[mi][nj][2], v3 = acc[mi][nj][3];
                        sum += v0 + v1 + v2 + v3;
                        sum2 = fmaf(v0, v0, sum2); sum2 = fmaf(v1, v1, sum2);
                        sum2 = fmaf(v2, v2, sum2); sum2 = fmaf(v3, v3, sum2);
                        const int s0 = mi*2, s1 = mi*2 + 1;
                        if (v0 < rE[s0]){ rE[s0] = v0; rI[s0] = k0;   }
                        if (v1 < rE[s0]){ rE[s0] = v1; rI[s0] = k0+1; }
                        if (v2 < rE[s1]){ rE[s1] = v2; rI[s1] = k0;   }
                        if (v3 < rE[s1]){ rE[s1] = v3; rI[s1] = k0+1; }
                    }
            }
        }

        // ---- cross-lane (quad) reduce, write candidates (pair-local rows) ----
        #pragma unroll
        for (int s4 = 0; s4 < 4; ++s4){
            float ev = rE[s4]; int ei = rI[s4];
            #pragma unroll
            for (int off = 1; off <= 2; off <<= 1){
                float ov = __shfl_xor_sync(0xffffffffu, ev, off);
                int   oi = __shfl_xor_sync(0xffffffffu, ei, off);
                bool take = wantMin ? (ov < ev || (ov == ev && oi < ei))
                                    : (ov > ev || (ov == ev && oi < ei));
                if (take){ ev = ov; ei = oi; }
            }
            if ((lane & 3) == 0){
                int row = warpM*32 + (s4 >> 1)*16 + (s4 & 1)*8 + q;
                cand[row*2 + warpN] = make_float2(ev, __int_as_float(ei));
            }
        }

        // convert next tile into the other A buffer (pair-local rows)
        if (t+1 < TTILES)
            storeSplits(sm, SM_A + (uint32_t)((t+1)&1)*A_BUF, xr, pair, pairTid);

        PBAR(pair);   // pair-local: covers cand(t) AND this pair's A(t+1)

        // ---- merge across the two n-warps, write staged outputs ----
        if (pairTid < 32){
            const int r_ = pair*32 + pairTid;
            float2 c0 = cand[r_*2 + 0], c1 = cand[r_*2 + 1];
            float ev = c0.x; int ei = __float_as_int(c0.y);
            int   oi = __float_as_int(c1.y);
            bool take = wantMin ? (c1.x < ev || (c1.x == ev && oi < ei))
                                : (c1.x > ev || (c1.x == ev && oi < ei));
            if (take){ ev = c1.x; ei = oi; }
            const int b = (gx*TTILES + t)*128 + r_;
            int code; float sv;
            if (gmm != 0.f){ code = ei; sv = ev;  }
            else           { code = 0;  sv = 0.f; }
            g_codei[(size_t)c*BB + b] = code;
            g_selv [(size_t)c*BB + b] = sv;
        }
    }

    // ---- per-block stats partial (deterministic) ----
    #pragma unroll
    for (int off = 16; off; off >>= 1){
        sum  += __shfl_xor_sync(0xffffffffu, sum,  off);
        sum2 += __shfl_xor_sync(0xffffffffu, sum2, off);
    }
    float2* red = (float2*)(sm + SM_RED);
    if (lane == 0) red[wid] = make_float2(sum, sum2);
    __syncthreads();
    if (tid == 0){
        float s = 0.f, s2 = 0.f;
        #pragma unroll
        for (int w = 0; w < 8; ++w){ s += red[w].x; s2 += red[w].y; }
        g_part[c*NGX + gx] = make_float2(s, s2);
    }
}

// ---------------------------------------------------------------------------
// Prep: centroid bf16 3-way splits + centroids passthrough to out
// ---------------------------------------------------------------------------
__global__ void prep_kernel(const float4* __restrict__ cent,
                            float4* __restrict__ outc){
    int i = blockIdx.x*256 + threadIdx.x;    // < NCENT/4
    float4 v = cent[i];
    outc[i] = v;
    float f[4] = {v.x, v.y, v.z, v.w};
    __nv_bfloat16 h[4], m[4], l[4];
    #pragma unroll
    for (int p = 0; p < 4; ++p) split3(f[p], h[p], m[p], l[p]);
    ((uint2*)g_cb0)[i] = make_uint2(pk(h[0],h[1]), pk(h[2],h[3]));
    ((uint2*)g_cb1)[i] = make_uint2(pk(m[0],m[1]), pk(m[2],m[3]));
    ((uint2*)g_cb2)[i] = make_uint2(pk(l[0],l[1]), pk(l[2],l[3]));
}

// ---------------------------------------------------------------------------
// Stats reduce: 16 partials per channel -> mean, invstd
// ---------------------------------------------------------------------------
__global__ void pass2_kernel(){
    int c = threadIdx.x;
    if (c < CC){
        double s = 0.0, s2 = 0.0;
        for (int i = 0; i < NGX; ++i){
            float2 p = g_part[c*NGX + i];
            s += (double)p.x; s2 += (double)p.y;
        }
        const double cnt = (double)BB*(double)KK;
        double mean = s / cnt;
        double var  = s2 / cnt - mean*mean;
        g_mean[c]   = (float)mean;
        g_invstd[c] = rsqrtf((float)var + 1e-5f);
    }
}

// ---------------------------------------------------------------------------
// Finalize: normalize selected values, transpose [c][b] -> [b][c], write out
// ---------------------------------------------------------------------------
__global__ __launch_bounds__(256)
void pass3_kernel(const float* __restrict__ gamma, const float* __restrict__ beta,
                  float* __restrict__ out){
    __shared__ float tc[16][65];
    __shared__ float tv[16][65];
    const int tid = threadIdx.x;
    const int b0  = blockIdx.x*16;
    #pragma unroll
    for (int i = 0; i < 4; ++i){
        int flat = i*256 + tid;           // 0..1023
        int cc = flat >> 4, bq = flat & 15;
        int b  = b0 + bq;
        float g = gamma[cc];
        int  code = g_codei[(size_t)cc*BB + b];
        float val;
        if (g != 0.f)
            val = (g_selv[(size_t)cc*BB + b] - g_mean[cc])*g_invstd[cc]*g + beta[cc];
        else
            val = beta[cc];
        tc[bq][cc] = (float)code;
        tv[bq][cc] = val;
    }
    __syncthreads();
    #pragma unroll
    for (int i = 0; i < 4; ++i){
        int flat = i*256 + tid;
        int row = flat >> 6, cc = flat & 63;
        size_t o = (size_t)(b0 + row)*CC + cc;
        out[o]      = tc[row][cc];
        out[N1 + o] = tv[row][cc];
    }
}

// ---------------------------------------------------------------------------
extern "C" void kernel_launch(void* const* d_in, const int* in_sizes, int n_in,
                              void* d_out, int out_size){
    (void)in_sizes; (void)n_in; (void)out_size;
    const float* x     = (const float*)d_in[0];
    const float* cent  = (const float*)d_in[1];
    const float* gamma = (const float*)d_in[2];
    const float* beta  = (const float*)d_in[3];
    float* out = (float*)d_out;

    cudaFuncSetAttribute(mma_kernel,
                         cudaFuncAttributeMaxDynamicSharedMemorySize, SM_TOTAL);

    prep_kernel<<<NCENT/4/256, 256>>>((const float4*)cent,
                                      (float4*)(out + 2*(size_t)N1));
    mma_kernel<<<dim3(NGX, CC), 256, SM_TOTAL>>>(x, gamma);
    pass2_kernel<<<1, 64>>>();
    pass3_kernel<<<BB/16, 256>>>(gamma, beta, out);
}

// round 12
// speedup vs baseline: 1.4355x; 1.3373x over previous
#include <cuda_runtime.h>
#include <cuda_fp16.h>
#include <cstdint>
#include <cfloat>

// Problem constants
#define BB 8192
#define CC 64
#define KK 256
#define DD 64
#define N1 (BB*CC)            // 524288
#define NCENT (CC*KK*DD)      // 1048576
#define TTILES 4
#define NGX 16                // BB / (128*TTILES)

// -------- static device scratch (no allocations allowed) --------
__device__ __align__(16) __half g_ch[NCENT];   // h split, [c][k][d]
__device__ __align__(16) __half g_cl[NCENT];   // l split (residual)
__device__ int    g_codei[N1];     // [c][b]
__device__ float  g_selv[N1];      // [c][b]
__device__ float2 g_part[CC*NGX];
__device__ float  g_mean[CC];
__device__ float  g_invstd[CC];

// ---------------- smem layout (dynamic) ----------------
#define SM_B      0u        // 2 splits x 32768  (256 rows x 128B, swizzled)
#define SM_A      65536u    // 2 bufs x 2 splits x 16384
#define A_BUF     32768u
#define A_SPLIT   16384u
#define SM_CAND   131072u   // 2 bufs x (128 rows x 2 warpN x float2)
#define CAND_BUF  2048u
#define SM_RED    135168u   // 8 x float2
#define SM_TOTAL  135232u

#define SWZ(o) ((uint32_t)(o) ^ ((((uint32_t)(o))>>3)&0x70u))

// per-warp-pair named barrier (64 threads; ids 1..4)
#define PBAR(p) asm volatile("bar.sync %0, 64;" :: "r"((p)+1) : "memory")

// ---------------- PTX helpers (portable sm_80+ only) ----------------
static __device__ __forceinline__ uint32_t smem_u32(const void* p){
    uint32_t a;
    asm("{ .reg .u64 t; cvta.to.shared.u64 t, %1; cvt.u32.u64 %0, t; }"
        : "=r"(a) : "l"(p));
    return a;
}
static __device__ __forceinline__ void ldsm4(uint32_t* r, uint32_t addr){
    asm volatile("ldmatrix.sync.aligned.m8n8.x4.shared.b16 {%0,%1,%2,%3}, [%4];"
        : "=r"(r[0]), "=r"(r[1]), "=r"(r[2]), "=r"(r[3]) : "r"(addr));
}
static __device__ __forceinline__ void mma16816(float* c, const uint32_t* a,
                                                uint32_t b0, uint32_t b1){
    asm volatile(
        "mma.sync.aligned.m16n8k16.row.col.f32.f16.f16.f32 "
        "{%0,%1,%2,%3}, {%4,%5,%6,%7}, {%8,%9}, {%0,%1,%2,%3};"
        : "+f"(c[0]), "+f"(c[1]), "+f"(c[2]), "+f"(c[3])
        : "r"(a[0]), "r"(a[1]), "r"(a[2]), "r"(a[3]), "r"(b0), "r"(b1));
}

// ---------------- conversion helpers ----------------
// fp16 2-way split: x = h + l + r2, |r2| <= 2^-22 |x|.
// All four cross-products are computed (l*l kept), so only r2-level terms
// are neglected (~1.7e-7 RMS per dot) — within the established noise floor.
static __device__ __forceinline__ void split2(float x, __half& h, __half& l){
    h = __float2half_rn(x);
    l = __float2half_rn(x - __half2float(h));
}
static __device__ __forceinline__ uint32_t pk(__half a, __half b){
    __half2 t = __halves2half2(a, b);
    return *reinterpret_cast<uint32_t*>(&t);
}

// ---- pair-local x load: each 64-thread pair loads its own 32 A-rows ----
static __device__ __forceinline__ void loadX(float4* xr, const float* __restrict__ x,
                                             int gx, int c, int t,
                                             int pair, int pairTid){
    const int b0 = (gx*TTILES + t)*128;
    const int f4 = pairTid & 15;
    #pragma unroll
    for (int i = 0; i < 8; ++i){
        int row = pair*32 + i*4 + (pairTid >> 4);
        xr[i] = ((const float4*)x)[((size_t)(b0+row)*CC + c)*(DD/4) + f4];
    }
}
// ---- pair-local convert: registers -> 2 fp16 splits in smem buffer ----
static __device__ __forceinline__ void storeSplits(char* sm, uint32_t abase,
                                                   const float4* xr,
                                                   int pair, int pairTid){
    const int f4 = pairTid & 15;
    #pragma unroll
    for (int i = 0; i < 8; ++i){
        int row = pair*32 + i*4 + (pairTid >> 4);
        float f[4] = {xr[i].x, xr[i].y, xr[i].z, xr[i].w};
        __half h[4], l[4];
        #pragma unroll
        for (int p = 0; p < 4; ++p) split2(f[p], h[p], l[p]);
        uint32_t so = SWZ(row*128 + f4*8);
        *(uint2*)(sm + abase + so)           = make_uint2(pk(h[0],h[1]), pk(h[2],h[3]));
        *(uint2*)(sm + abase + A_SPLIT + so) = make_uint2(pk(l[0],l[1]), pk(l[2],l[3]));
    }
}

// ---------------------------------------------------------------------------
// Main kernel: grid (NGX, CC), 256 threads, warp grid 4(m) x 2(n),
// warp tile 32x64, N in two 128-halves. 4-pass fp16 2-split GEMM on mma.sync:
//   sb=1 (l'): {l*l', h*l'}   sb=0 (h'): {l*h', h*h'}   (small terms first)
// Each 64-thread warp-pair owns its 32 A rows end-to-end (pair-local barrier).
// ---------------------------------------------------------------------------
__global__ __launch_bounds__(256, 1)
void mma_kernel(const float* __restrict__ x, const float* __restrict__ gamma){
    extern __shared__ __align__(16) char sm[];
    const uint32_t smb = smem_u32(sm);
    const int tid = threadIdx.x, lane = tid & 31, wid = tid >> 5;
    const int warpM = wid >> 1, warpN = wid & 1, q = lane >> 2;
    const int pair = warpM, pairTid = tid & 63;
    const int gx = blockIdx.x, c = blockIdx.y;

    // ---- load 2 B splits into swizzled smem (64KB, whole block) ----
    {
        const uint4* cbh = (const uint4*)g_ch;
        const uint4* cbl = (const uint4*)g_cl;
        #pragma unroll
        for (int i = 0; i < 16; ++i){
            int flat = i*256 + tid;          // 0..4095
            int s    = flat >> 11;
            int g    = flat & 2047;
            int row  = g >> 3, q8 = g & 7;
            const uint4* src = s ? cbl : cbh;
            uint4 v = src[((size_t)c*KK + row)*8 + q8];
            *(uint4*)(sm + SM_B + (uint32_t)s*32768u + SWZ(row*128 + q8*16)) = v;
        }
    }

    const float gmm = gamma[c];
    const bool wantMin = (gmm < 0.f);
    float sum = 0.f, sum2 = 0.f;

    // per-lane ldmatrix address components
    const uint32_t aRow  = (uint32_t)(warpM*32 + (lane & 15));
    const uint32_t aCol  = (uint32_t)((lane >> 4) << 4);       // 0 or 16 bytes
    const uint32_t bRowL = (uint32_t)(((lane >> 4) << 3) + (lane & 7));
    const uint32_t bCol  = (uint32_t)((lane & 8) << 1);        // 0 or 16 bytes

    // 4-pass tables grouped by B split (low-magnitude first within each group)
    const int SBt[2] = {1, 0};           // B: l' group, then h' group
    const int SAt[2][2] = {{1,0},{1,0}}; // A within group: l, then h

    // prologue: load + convert tile 0 (pair-local rows); full sync covers B too
    float4 xr[8];
    loadX(xr, x, gx, c, 0, pair, pairTid);
    storeSplits(sm, SM_A, xr, pair, pairTid);
    __syncthreads();

    #pragma unroll 1
    for (int t = 0; t < TTILES; ++t){
        // prefetch next x tile into registers (hidden under compute)
        if (t+1 < TTILES) loadX(xr, x, gx, c, t+1, pair, pairTid);

        const uint32_t abase = SM_A + (uint32_t)(t&1)*A_BUF;
        float2* cand = (float2*)(sm + SM_CAND + (uint32_t)(t&1)*CAND_BUF);

        // single-extremum running candidates per owned row-slot
        float rE[4]; int rI[4];
        #pragma unroll
        for (int s4 = 0; s4 < 4; ++s4){
            rE[s4] = wantMin ? FLT_MAX : -FLT_MAX; rI[s4] = 0;
        }

        #pragma unroll
        for (int nh = 0; nh < 2; ++nh){
            float acc[2][8][4];
            #pragma unroll
            for (int mi = 0; mi < 2; ++mi)
                #pragma unroll
                for (int nj = 0; nj < 8; ++nj)
                    #pragma unroll
                    for (int e = 0; e < 4; ++e) acc[mi][nj][e] = 0.f;

            #pragma unroll
            for (int ks = 0; ks < 4; ++ks){
                uint32_t aF[2][2][4];
                #pragma unroll
                for (int s = 0; s < 2; ++s)
                    #pragma unroll
                    for (int mi = 0; mi < 2; ++mi)
                        ldsm4(aF[s][mi], smb + abase + (uint32_t)s*A_SPLIT +
                              SWZ(aRow*128u + (uint32_t)mi*2048u +
                                  (uint32_t)ks*32u + aCol));
                #pragma unroll
                for (int g3 = 0; g3 < 2; ++g3){
                    const int sb = SBt[g3];
                    uint32_t bF[4][4];
                    #pragma unroll
                    for (int njp = 0; njp < 4; ++njp)
                        ldsm4(bF[njp], smb + SM_B + (uint32_t)sb*32768u +
                              SWZ((uint32_t)(nh*128 + warpN*64 + njp*16 + bRowL)*128u +
                                  (uint32_t)ks*32u + bCol));
                    #pragma unroll
                    for (int pi = 0; pi < 2; ++pi){
                        const int sa = SAt[g3][pi];
                        #pragma unroll
                        for (int mi = 0; mi < 2; ++mi)
                            #pragma unroll
                            for (int njp = 0; njp < 4; ++njp){
                                mma16816(acc[mi][2*njp],   aF[sa][mi], bF[njp][0], bF[njp][1]);
                                mma16816(acc[mi][2*njp+1], aF[sa][mi], bF[njp][2], bF[njp][3]);
                            }
                    }
                }
            }

            // ---- epilogue scan (uniform branch: track only needed extremum) ----
            const int kbase = nh*128 + warpN*64 + 2*(lane & 3);
            if (!wantMin){
                #pragma unroll
                for (int mi = 0; mi < 2; ++mi)
                    #pragma unroll
                    for (int nj = 0; nj < 8; ++nj){
                        const int k0 = kbase + nj*8;
                        float v0 = acc[mi][nj][0], v1 = acc[mi][nj][1];
                        float v2 = acc[mi][nj][2], v3 = acc[mi][nj][3];
                        sum += v0 + v1 + v2 + v3;
                        sum2 = fmaf(v0, v0, sum2); sum2 = fmaf(v1, v1, sum2);
                        sum2 = fmaf(v2, v2, sum2); sum2 = fmaf(v3, v3, sum2);
                        const int s0 = mi*2, s1 = mi*2 + 1;
                        if (v0 > rE[s0]){ rE[s0] = v0; rI[s0] = k0;   }
                        if (v1 > rE[s0]){ rE[s0] = v1; rI[s0] = k0+1; }
                        if (v2 > rE[s1]){ rE[s1] = v2; rI[s1] = k0;   }
                        if (v3 > rE[s1]){ rE[s1] = v3; rI[s1] = k0+1; }
                    }
            } else {
                #pragma unroll
                for (int mi = 0; mi < 2; ++mi)
                    #pragma unroll
                    for (int nj = 0; nj < 8; ++nj){
                        const int k0 = kbase + nj*8;
                        float v0 = acc[mi][nj][0], v1 = acc[mi][nj][1];
                        float v2 = acc[mi][nj][2], v3 = acc[mi][nj][3];
                        sum += v0 + v1 + v2 + v3;
                        sum2 = fmaf(v0, v0, sum2); sum2 = fmaf(v1, v1, sum2);
                        sum2 = fmaf(v2, v2, sum2); sum2 = fmaf(v3, v3, sum2);
                        const int s0 = mi*2, s1 = mi*2 + 1;
                        if (v0 < rE[s0]){ rE[s0] = v0; rI[s0] = k0;   }
                        if (v1 < rE[s0]){ rE[s0] = v1; rI[s0] = k0+1; }
                        if (v2 < rE[s1]){ rE[s1] = v2; rI[s1] = k0;   }
                        if (v3 < rE[s1]){ rE[s1] = v3; rI[s1] = k0+1; }
                    }
            }
        }

        // ---- cross-lane (quad) reduce, write candidates (pair-local rows) ----
        #pragma unroll
        for (int s4 = 0; s4 < 4; ++s4){
            float ev = rE[s4]; int ei = rI[s4];
            #pragma unroll
            for (int off = 1; off <= 2; off <<= 1){
                float ov = __shfl_xor_sync(0xffffffffu, ev, off);
                int   oi = __shfl_xor_sync(0xffffffffu, ei, off);
                bool take = wantMin ? (ov < ev || (ov == ev && oi < ei))
                                    : (ov > ev || (ov == ev && oi < ei));
                if (take){ ev = ov; ei = oi; }
            }
            if ((lane & 3) == 0){
                int row = warpM*32 + (s4 >> 1)*16 + (s4 & 1)*8 + q;
                cand[row*2 + warpN] = make_float2(ev, __int_as_float(ei));
            }
        }

        // convert next tile into the other A buffer (pair-local rows)
        if (t+1 < TTILES)
            storeSplits(sm, SM_A + (uint32_t)((t+1)&1)*A_BUF, xr, pair, pairTid);

        PBAR(pair);   // pair-local: covers cand(t) AND this pair's A(t+1)

        // ---- merge across the two n-warps, write staged outputs ----
        if (pairTid < 32){
            const int r_ = pair*32 + pairTid;
            float2 c0 = cand[r_*2 + 0], c1 = cand[r_*2 + 1];
            float ev = c0.x; int ei = __float_as_int(c0.y);
            int   oi = __float_as_int(c1.y);
            bool take = wantMin ? (c1.x < ev || (c1.x == ev && oi < ei))
                                : (c1.x > ev || (c1.x == ev && oi < ei));
            if (take){ ev = c1.x; ei = oi; }
            const int b = (gx*TTILES + t)*128 + r_;
            int code; float sv;
            if (gmm != 0.f){ code = ei; sv = ev;  }
            else           { code = 0;  sv = 0.f; }
            g_codei[(size_t)c*BB + b] = code;
            g_selv [(size_t)c*BB + b] = sv;
        }
    }

    // ---- per-block stats partial (deterministic) ----
    #pragma unroll
    for (int off = 16; off; off >>= 1){
        sum  += __shfl_xor_sync(0xffffffffu, sum,  off);
        sum2 += __shfl_xor_sync(0xffffffffu, sum2, off);
    }
    float2* red = (float2*)(sm + SM_RED);
    if (lane == 0) red[wid] = make_float2(sum, sum2);
    __syncthreads();
    if (tid == 0){
        float s = 0.f, s2 = 0.f;
        #pragma unroll
        for (int w = 0; w < 8; ++w){ s += red[w].x; s2 += red[w].y; }
        g_part[c*NGX + gx] = make_float2(s, s2);
    }
}

// ---------------------------------------------------------------------------
// Prep: centroid fp16 2-way splits + centroids passthrough to out
// ---------------------------------------------------------------------------
__global__ void prep_kernel(const float4* __restrict__ cent,
                            float4* __restrict__ outc){
    int i = blockIdx.x*256 + threadIdx.x;    // < NCENT/4
    float4 v = cent[i];
    outc[i] = v;
    float f[4] = {v.x, v.y, v.z, v.w};
    __half h[4], l[4];
    #pragma unroll
    for (int p = 0; p < 4; ++p) split2(f[p], h[p], l[p]);
    ((uint2*)g_ch)[i] = make_uint2(pk(h[0],h[1]), pk(h[2],h[3]));
    ((uint2*)g_cl)[i] = make_uint2(pk(l[0],l[1]), pk(l[2],l[3]));
}

// ---------------------------------------------------------------------------
// Stats reduce: 16 partials per channel -> mean, invstd
// ---------------------------------------------------------------------------
__global__ void pass2_kernel(){
    int c = threadIdx.x;
    if (c < CC){
        double s = 0.0, s2 = 0.0;
        for (int i = 0; i < NGX; ++i){
            float2 p = g_part[c*NGX + i];
            s += (double)p.x; s2 += (double)p.y;
        }
        const double cnt = (double)BB*(double)KK;
        double mean = s / cnt;
        double var  = s2 / cnt - mean*mean;
        g_mean[c]   = (float)mean;
        g_invstd[c] = rsqrtf((float)var + 1e-5f);
    }
}

// ---------------------------------------------------------------------------
// Finalize: normalize selected values, transpose [c][b] -> [b][c], write out
// ---------------------------------------------------------------------------
__global__ __launch_bounds__(256)
void pass3_kernel(const float* __restrict__ gamma, const float* __restrict__ beta,
                  float* __restrict__ out){
    __shared__ float tc[16][65];
    __shared__ float tv[16][65];
    const int tid = threadIdx.x;
    const int b0  = blockIdx.x*16;
    #pragma unroll
    for (int i = 0; i < 4; ++i){
        int flat = i*256 + tid;           // 0..1023
        int cc = flat >> 4, bq = flat & 15;
        int b  = b0 + bq;
        float g = gamma[cc];
        int  code = g_codei[(size_t)cc*BB + b];
        float val;
        if (g != 0.f)
            val = (g_selv[(size_t)cc*BB + b] - g_mean[cc])*g_invstd[cc]*g + beta[cc];
        else
            val = beta[cc];
        tc[bq][cc] = (float)code;
        tv[bq][cc] = val;
    }
    __syncthreads();
    #pragma unroll
    for (int i = 0; i < 4; ++i){
        int flat = i*256 + tid;
        int row = flat >> 6, cc = flat & 63;
        size_t o = (size_t)(b0 + row)*CC + cc;
        out[o]      = tc[row][cc];
        out[N1 + o] = tv[row][cc];
    }
}

// ---------------------------------------------------------------------------
extern "C" void kernel_launch(void* const* d_in, const int* in_sizes, int n_in,
                              void* d_out, int out_size){
    (void)in_sizes; (void)n_in; (void)out_size;
    const float* x     = (const float*)d_in[0];
    const float* cent  = (const float*)d_in[1];
    const float* gamma = (const float*)d_in[2];
    const float* beta  = (const float*)d_in[3];
    float* out = (float*)d_out;

    cudaFuncSetAttribute(mma_kernel,
                         cudaFuncAttributeMaxDynamicSharedMemorySize, SM_TOTAL);

    prep_kernel<<<NCENT/4/256, 256>>>((const float4*)cent,
                                      (float4*)(out + 2*(size_t)N1));
    mma_kernel<<<dim3(NGX, CC), 256, SM_TOTAL>>>(x, gamma);
    pass2_kernel<<<1, 64>>>();
    pass3_kernel<<<BB/16, 256>>>(gamma, beta, out);
}